// round 12
// baseline (speedup 1.0000x reference)
#include <cuda_runtime.h>
#include <cstdint>

#define N_NODES 50000
#define N_EDGES 800000
#define IN_CH   100
#define HID     128
#define OUT_CH  47
#define OUT_P   48
#define ORIG    25000
#define CAP     96            // bucket capacity (max degree; Poisson(16) tail ~0)

#define PRE_NB  196
#define PRE_BS  256

#define K1    208         // padded K for layer1 (104 agg + 104 x)
#define K1C   13          // chunks of 16
#define K2C   8           // chunks of 16
#define N2    96          // layer2 N: 48 g0-cols + 48 r0-cols
#define SB1   132         // sB row stride gemm1
#define SB2   100         // sB row stride gemm2

// ---- scratch ----
__device__ int    g_cnt [N_NODES];
__device__ int    g_adj [(size_t)N_NODES * CAP];     // bucketed adjacency
__device__ float  g_agg1[(size_t)N_NODES * IN_CH];
__device__ float  g_h   [(size_t)N_NODES * HID];
__device__ float  g_g0  [(size_t)N_NODES * OUT_P];   // stride 48 (col 47 pad)
__device__ float  g_r0  [(size_t)ORIG * OUT_P];
__device__ float  g_B1  [K1 * HID];                  // tf32 [208][128]
__device__ float  g_B2  [HID * N2];                  // tf32 [128][96]

static __device__ __forceinline__ float to_tf32(float f) {
    uint32_t o;
    asm("cvt.rna.tf32.f32 %0, %1;" : "=r"(o) : "f"(f));
    return __uint_as_float(o);
}
static __device__ __forceinline__ void mma_tf32(float* c, uint32_t a0, uint32_t a1,
                                                uint32_t a2, uint32_t a3,
                                                uint32_t b0, uint32_t b1) {
    asm("mma.sync.aligned.m16n8k8.row.col.f32.tf32.tf32.f32 "
        "{%0,%1,%2,%3},{%4,%5,%6,%7},{%8,%9},{%0,%1,%2,%3};"
        : "+f"(c[0]), "+f"(c[1]), "+f"(c[2]), "+f"(c[3])
        : "r"(a0), "r"(a1), "r"(a2), "r"(a3), "r"(b0), "r"(b1));
}
static __device__ __forceinline__ void cpa16(uint32_t dst, const void* src, bool p) {
    int sz = p ? 16 : 0;
    asm volatile("cp.async.cg.shared.global [%0], [%1], 16, %2;"
                 :: "r"(dst), "l"(src), "r"(sz));
}
static __device__ __forceinline__ void cpa_commit() {
    asm volatile("cp.async.commit_group;");
}
static __device__ __forceinline__ void cpa_wait2() {
    asm volatile("cp.async.wait_group 2;");
}

// ---- 1. zero counters + prepack B1/B2 (tf32) ----
__global__ void k_pre(const float* __restrict__ w1l, const float* __restrict__ w1r,
                      const float* __restrict__ w2l, const float* __restrict__ w2r) {
    int i = blockIdx.x * blockDim.x + threadIdx.x;
    if (i < N_NODES) g_cnt[i] = 0;
    if (i < K1 * HID) {
        int k = i / HID, c = i % HID;
        float v = 0.f;
        if (k < IN_CH)                         v = w1l[k * HID + c];
        else if (k >= 104 && k < 104 + IN_CH)  v = w1r[(k - 104) * HID + c];
        g_B1[i] = to_tf32(v);
    }
    if (i < HID * N2) {
        int k = i / N2, c = i % N2;
        float v = 0.f;
        if (c < OUT_CH)                        v = w2l[k * OUT_CH + c];
        else if (c >= 48 && c < 48 + OUT_CH)   v = w2r[k * OUT_CH + (c - 48)];
        g_B2[i] = to_tf32(v);
    }
}

// ---- 2. single-pass bucketed fill: count + scatter in one edge pass ----
__global__ void k_fillb(const int* __restrict__ src, const int* __restrict__ dst) {
    int i = blockIdx.x * blockDim.x + threadIdx.x;
    if (i < N_EDGES) {
        int d = dst[i];
        int p = atomicAdd(&g_cnt[d], 1);
        if (p < CAP) g_adj[(size_t)d * CAP + p] = src[i];
    }
}

// ---- 3. layer-1 mean aggregation (warp/node, fp32) ----
__global__ void k_agg1(const float* __restrict__ x) {
    int w    = (blockIdx.x * blockDim.x + threadIdx.x) >> 5;
    int lane = threadIdx.x & 31;
    if (w >= N_NODES) return;
    int deg = g_cnt[w];
    if (deg > CAP) deg = CAP;
    const int* adj = g_adj + (size_t)w * CAP;
    float4 acc = make_float4(0.f, 0.f, 0.f, 0.f);
    for (int e = 0; e < deg; e++) {
        int s = adj[e];
        if (lane < IN_CH / 4) {
            float4 v = reinterpret_cast<const float4*>(x + (size_t)s * IN_CH)[lane];
            acc.x += v.x; acc.y += v.y; acc.z += v.z; acc.w += v.w;
        }
    }
    float inv = 1.f / fmaxf((float)deg, 1.f);
    if (lane < IN_CH / 4) {
        acc.x *= inv; acc.y *= inv; acc.z *= inv; acc.w *= inv;
        reinterpret_cast<float4*>(g_agg1 + (size_t)w * IN_CH)[lane] = acc;
    }
}

// ---- 4. layer-1 GEMM, tf32 mma, K=16 chunks, 4-stage cp.async pipeline ----
__global__ void __launch_bounds__(256) k_gemm1(const float* __restrict__ x,
                                               const float* __restrict__ b1l) {
    __shared__ float sA[4][128 * 16];
    __shared__ float sB[4][16 * SB1];
    const int tid  = threadIdx.x;
    const int lane = tid & 31;
    const int warp = tid >> 5;
    const int wm   = warp & 3;
    const int wn   = warp >> 2;
    const int gr   = lane >> 2;
    const int kc   = lane & 3;
    const int row0 = blockIdx.x * 128;

    const int srow = tid >> 1;           // 0..127
    const int skq  = (tid & 1) * 4;      // 0 or 4
    const int bk   = tid >> 4;           // 0..15
    const int bn0  = (tid & 15) * 8;     // 0..120
    const int node = row0 + srow;

    // issue one K=16 chunk (2x A float4 + 2x B float4 per thread)
    auto issue = [&](int cc) {
        int st = cc & 3;
        int k0 = cc * 16;
#pragma unroll
        for (int q = 0; q < 2; q++) {
            int ks = k0 + skq + q * 8;
            const float* pa = g_agg1;
            bool va = false;
            if (node < N_NODES) {
                if (ks < IN_CH)                 { pa = g_agg1 + (size_t)node * IN_CH + ks; va = true; }
                else if (ks >= 104 && ks < 204) { pa = x + (size_t)node * IN_CH + (ks - 104); va = true; }
            }
            cpa16((uint32_t)__cvta_generic_to_shared(&sA[st][srow * 16 + skq + q * 8]), pa, va);
        }
        cpa16((uint32_t)__cvta_generic_to_shared(&sB[st][bk * SB1 + bn0]),
              g_B1 + (k0 + bk) * HID + bn0, true);
        cpa16((uint32_t)__cvta_generic_to_shared(&sB[st][bk * SB1 + bn0 + 4]),
              g_B1 + (k0 + bk) * HID + bn0 + 4, true);
    };

    issue(0); cpa_commit();
    issue(1); cpa_commit();
    issue(2); cpa_commit();

    float acc[2][8][4];
#pragma unroll
    for (int mt = 0; mt < 2; mt++)
#pragma unroll
        for (int nt = 0; nt < 8; nt++)
#pragma unroll
            for (int j = 0; j < 4; j++) acc[mt][nt][j] = 0.f;

#pragma unroll 1
    for (int c = 0; c < K1C; c++) {
        cpa_wait2();
        __syncthreads();
        const float* A = sA[c & 3];
        const float* B = sB[c & 3];

#pragma unroll
        for (int kk = 0; kk < 2; kk++) {
            int kb = kk * 8;
            uint32_t afr[2][4];
#pragma unroll
            for (int mt = 0; mt < 2; mt++) {
                int ar = wm * 32 + mt * 16 + gr;
                afr[mt][0] = __float_as_uint(A[ar * 16 + kb + kc]);
                afr[mt][1] = __float_as_uint(A[(ar + 8) * 16 + kb + kc]);
                afr[mt][2] = __float_as_uint(A[ar * 16 + kb + kc + 4]);
                afr[mt][3] = __float_as_uint(A[(ar + 8) * 16 + kb + kc + 4]);
            }
#pragma unroll
            for (int nt = 0; nt < 8; nt++) {
                int bc = wn * 64 + nt * 8 + gr;
                uint32_t b0 = __float_as_uint(B[(kb + kc) * SB1 + bc]);
                uint32_t b1 = __float_as_uint(B[(kb + kc + 4) * SB1 + bc]);
                mma_tf32(acc[0][nt], afr[0][0], afr[0][1], afr[0][2], afr[0][3], b0, b1);
                mma_tf32(acc[1][nt], afr[1][0], afr[1][1], afr[1][2], afr[1][3], b0, b1);
            }
        }

        if (c + 3 < K1C) issue(c + 3);
        cpa_commit();
    }

#pragma unroll
    for (int mt = 0; mt < 2; mt++) {
#pragma unroll
        for (int nt = 0; nt < 8; nt++) {
            int col = wn * 64 + nt * 8 + 2 * kc;
            float2 bv = *reinterpret_cast<const float2*>(b1l + col);
            int r1 = row0 + wm * 32 + mt * 16 + gr;
            if (r1 < N_NODES) {
                float2 o = make_float2(acc[mt][nt][0] + bv.x, acc[mt][nt][1] + bv.y);
                *reinterpret_cast<float2*>(g_h + (size_t)r1 * HID + col) = o;
            }
            int r2 = r1 + 8;
            if (r2 < N_NODES) {
                float2 o = make_float2(acc[mt][nt][2] + bv.x, acc[mt][nt][3] + bv.y);
                *reinterpret_cast<float2*>(g_h + (size_t)r2 * HID + col) = o;
            }
        }
    }
}

// ---- 5. layer-2 GEMM, tf32 mma, K=16 chunks, 4-stage cp.async pipeline ----
__global__ void __launch_bounds__(256) k_gemm2(const float* __restrict__ b2) {
    __shared__ float sA[4][128 * 16];
    __shared__ float sB[4][16 * SB2];
    const int tid  = threadIdx.x;
    const int lane = tid & 31;
    const int warp = tid >> 5;
    const int wm   = warp & 3;
    const int wn   = warp >> 2;
    const int gr   = lane >> 2;
    const int kc   = lane & 3;
    const int row0 = blockIdx.x * 128;

    const int srow = tid >> 1;
    const int skq  = (tid & 1) * 4;
    const int bk   = tid >> 4;           // 0..15
    const int bn0  = (tid & 15) * 8;     // 0..120; valid if < 96
    const bool doB = (tid & 15) < 12;
    const int node = row0 + srow;

    const bool active = (wn == 0) || (row0 < ORIG);

    auto issue = [&](int cc) {
        int st = cc & 3;
        int k0 = cc * 16;
        bool va = (node < N_NODES);
        const float* base = va ? (g_h + (size_t)node * HID + k0 + skq) : g_h;
        cpa16((uint32_t)__cvta_generic_to_shared(&sA[st][srow * 16 + skq]), base, va);
        cpa16((uint32_t)__cvta_generic_to_shared(&sA[st][srow * 16 + skq + 8]),
              va ? (base + 8) : g_h, va);
        if (doB) {
            cpa16((uint32_t)__cvta_generic_to_shared(&sB[st][bk * SB2 + bn0]),
                  g_B2 + (k0 + bk) * N2 + bn0, true);
            cpa16((uint32_t)__cvta_generic_to_shared(&sB[st][bk * SB2 + bn0 + 4]),
                  g_B2 + (k0 + bk) * N2 + bn0 + 4, true);
        }
    };

    issue(0); cpa_commit();
    issue(1); cpa_commit();
    issue(2); cpa_commit();

    float acc[2][6][4];
#pragma unroll
    for (int mt = 0; mt < 2; mt++)
#pragma unroll
        for (int nt = 0; nt < 6; nt++)
#pragma unroll
            for (int j = 0; j < 4; j++) acc[mt][nt][j] = 0.f;

#pragma unroll 1
    for (int c = 0; c < K2C; c++) {
        cpa_wait2();
        __syncthreads();
        const float* A = sA[c & 3];
        const float* B = sB[c & 3];

        if (active) {
#pragma unroll
            for (int kk = 0; kk < 2; kk++) {
                int kb = kk * 8;
                uint32_t afr[2][4];
#pragma unroll
                for (int mt = 0; mt < 2; mt++) {
                    int ar = wm * 32 + mt * 16 + gr;
                    afr[mt][0] = __float_as_uint(A[ar * 16 + kb + kc]);
                    afr[mt][1] = __float_as_uint(A[(ar + 8) * 16 + kb + kc]);
                    afr[mt][2] = __float_as_uint(A[ar * 16 + kb + kc + 4]);
                    afr[mt][3] = __float_as_uint(A[(ar + 8) * 16 + kb + kc + 4]);
                }
#pragma unroll
                for (int nt = 0; nt < 6; nt++) {
                    int bc = wn * 48 + nt * 8 + gr;
                    uint32_t b0 = __float_as_uint(B[(kb + kc) * SB2 + bc]);
                    uint32_t b1 = __float_as_uint(B[(kb + kc + 4) * SB2 + bc]);
                    mma_tf32(acc[0][nt], afr[0][0], afr[0][1], afr[0][2], afr[0][3], b0, b1);
                    mma_tf32(acc[1][nt], afr[1][0], afr[1][1], afr[1][2], afr[1][3], b0, b1);
                }
            }
        }

        if (c + 3 < K2C) issue(c + 3);
        cpa_commit();
    }

    if (!active) return;

#pragma unroll
    for (int mt = 0; mt < 2; mt++) {
#pragma unroll
        for (int nt = 0; nt < 6; nt++) {
            int colL = nt * 8 + 2 * kc;
            int r1 = row0 + wm * 32 + mt * 16 + gr;
            int r2 = r1 + 8;
            if (wn == 0) {
                if (r1 < N_NODES)
                    *reinterpret_cast<float2*>(g_g0 + (size_t)r1 * OUT_P + colL) =
                        make_float2(acc[mt][nt][0], acc[mt][nt][1]);
                if (r2 < N_NODES)
                    *reinterpret_cast<float2*>(g_g0 + (size_t)r2 * OUT_P + colL) =
                        make_float2(acc[mt][nt][2], acc[mt][nt][3]);
            } else {
                float bx = b2[colL];
                float by = (colL + 1 < OUT_CH) ? b2[colL + 1] : 0.f;
                if (r1 < ORIG)
                    *reinterpret_cast<float2*>(g_r0 + (size_t)r1 * OUT_P + colL) =
                        make_float2(acc[mt][nt][0] + bx, acc[mt][nt][1] + by);
                if (r2 < ORIG)
                    *reinterpret_cast<float2*>(g_r0 + (size_t)r2 * OUT_P + colL) =
                        make_float2(acc[mt][nt][2] + bx, acc[mt][nt][3] + by);
            }
        }
    }
}

// ---- 6. final: out = log_softmax(mean_nbr(g0) + r0)  for i < ORIG ----
__global__ void k_final(float* __restrict__ out) {
    int w    = (blockIdx.x * blockDim.x + threadIdx.x) >> 5;
    int lane = threadIdx.x & 31;
    if (w >= ORIG) return;
    int deg = g_cnt[w];
    if (deg > CAP) deg = CAP;
    const int* adj = g_adj + (size_t)w * CAP;
    float a0 = 0.f, a1 = 0.f;
    for (int e = 0; e < deg; e++) {
        int s = adj[e];
        const float* row = g_g0 + (size_t)s * OUT_P;
        a0 += __ldg(row + lane);
        if (lane < OUT_CH - 32) a1 += __ldg(row + 32 + lane);
    }
    float inv = 1.f / fmaxf((float)deg, 1.f);
    const float* r0row = g_r0 + (size_t)w * OUT_P;
    a0 = a0 * inv + r0row[lane];
    if (lane < OUT_CH - 32) a1 = a1 * inv + r0row[32 + lane];

    float m = a0;
    if (lane < OUT_CH - 32) m = fmaxf(m, a1);
#pragma unroll
    for (int o = 16; o > 0; o >>= 1) m = fmaxf(m, __shfl_xor_sync(0xffffffffu, m, o));
    float e0 = expf(a0 - m);
    float e1 = (lane < OUT_CH - 32) ? expf(a1 - m) : 0.f;
    float ss = e0 + e1;
#pragma unroll
    for (int o = 16; o > 0; o >>= 1) ss += __shfl_xor_sync(0xffffffffu, ss, o);
    float ls = m + logf(ss);
    out[(size_t)w * OUT_CH + lane] = a0 - ls;
    if (lane < OUT_CH - 32) out[(size_t)w * OUT_CH + 32 + lane] = a1 - ls;
}

extern "C" void kernel_launch(void* const* d_in, const int* in_sizes, int n_in,
                              void* d_out, int out_size) {
    const float* x   = (const float*)d_in[0];
    const int*   ei  = (const int*)  d_in[1];
    const int*   src = ei;
    const int*   dst = ei + N_EDGES;
    const float* w1l = (const float*)d_in[3];
    const float* b1l = (const float*)d_in[4];
    const float* w1r = (const float*)d_in[5];
    const float* w2l = (const float*)d_in[6];
    const float* b2l = (const float*)d_in[7];
    const float* w2r = (const float*)d_in[8];
    float* out = (float*)d_out;

    const int GB = (N_NODES + 127) / 128;   // 391

    k_pre   <<<PRE_NB, PRE_BS>>>(w1l, w1r, w2l, w2r);
    k_fillb <<<(N_EDGES + 255) / 256, 256>>>(src, dst);
    k_agg1  <<<(N_NODES * 32 + 255) / 256, 256>>>(x);
    k_gemm1 <<<GB, 256>>>(x, b1l);
    k_gemm2 <<<GB, 256>>>(b2l);
    k_final <<<(ORIG * 32 + 255) / 256, 256>>>(out);
}

// round 13
// speedup vs baseline: 1.1243x; 1.1243x over previous
#include <cuda_runtime.h>
#include <cstdint>

#define N_NODES 50000
#define N_EDGES 800000
#define IN_CH   100
#define HID     128
#define OUT_CH  47
#define OUT_P   48
#define ORIG    25000
#define CAP     96            // bucket capacity (max degree; Poisson(16) tail ~0)

#define PRE_NB  196
#define PRE_BS  256

#define K1   208          // padded K for layer1 (104 agg + 104 x)
#define K1C  (K1 / 8)     // 26 chunks
#define K2C  (HID / 8)    // 16 chunks
#define N2   96           // layer2 N: 48 g0-cols + 48 r0-cols
#define SB1  136          // sB row stride gemm1 (mod 32 == 8 -> conflict-free)
#define SB2  104          // sB row stride gemm2 (mod 32 == 8 -> conflict-free)

// ---- scratch ----
__device__ int    g_cnt [N_NODES];
__device__ int    g_adj [(size_t)N_NODES * CAP];     // bucketed adjacency
__device__ float  g_agg1[(size_t)N_NODES * IN_CH];
__device__ float  g_h   [(size_t)N_NODES * HID];
__device__ float  g_g0  [(size_t)N_NODES * OUT_P];   // stride 48 (col 47 pad)
__device__ float  g_r0  [(size_t)ORIG * OUT_P];
__device__ float  g_B1  [K1 * HID];                  // tf32 [208][128]
__device__ float  g_B2  [HID * N2];                  // tf32 [128][96]

static __device__ __forceinline__ float to_tf32(float f) {
    uint32_t o;
    asm("cvt.rna.tf32.f32 %0, %1;" : "=r"(o) : "f"(f));
    return __uint_as_float(o);
}
static __device__ __forceinline__ void mma_tf32(float* c, uint32_t a0, uint32_t a1,
                                                uint32_t a2, uint32_t a3,
                                                uint32_t b0, uint32_t b1) {
    asm("mma.sync.aligned.m16n8k8.row.col.f32.tf32.tf32.f32 "
        "{%0,%1,%2,%3},{%4,%5,%6,%7},{%8,%9},{%0,%1,%2,%3};"
        : "+f"(c[0]), "+f"(c[1]), "+f"(c[2]), "+f"(c[3])
        : "r"(a0), "r"(a1), "r"(a2), "r"(a3), "r"(b0), "r"(b1));
}
static __device__ __forceinline__ void cpa16(uint32_t dst, const void* src, bool p) {
    int sz = p ? 16 : 0;
    asm volatile("cp.async.cg.shared.global [%0], [%1], 16, %2;"
                 :: "r"(dst), "l"(src), "r"(sz));
}
static __device__ __forceinline__ void cpa_commit() {
    asm volatile("cp.async.commit_group;");
}
static __device__ __forceinline__ void cpa_wait2() {
    asm volatile("cp.async.wait_group 2;");
}
// swizzle of the 16B half for row r:  0 or 4 floats
static __device__ __forceinline__ int swz(int r) {
    return 4 * ((r & 1) ^ ((r >> 2) & 1));
}

// ---- 1. zero counters + prepack B1/B2 (tf32) ----
__global__ void k_pre(const float* __restrict__ w1l, const float* __restrict__ w1r,
                      const float* __restrict__ w2l, const float* __restrict__ w2r) {
    int i = blockIdx.x * blockDim.x + threadIdx.x;
    if (i < N_NODES) g_cnt[i] = 0;
    if (i < K1 * HID) {
        int k = i / HID, c = i % HID;
        float v = 0.f;
        if (k < IN_CH)                         v = w1l[k * HID + c];
        else if (k >= 104 && k < 104 + IN_CH)  v = w1r[(k - 104) * HID + c];
        g_B1[i] = to_tf32(v);
    }
    if (i < HID * N2) {
        int k = i / N2, c = i % N2;
        float v = 0.f;
        if (c < OUT_CH)                        v = w2l[k * OUT_CH + c];
        else if (c >= 48 && c < 48 + OUT_CH)   v = w2r[k * OUT_CH + (c - 48)];
        g_B2[i] = to_tf32(v);
    }
}

// ---- 2. single-pass bucketed fill: count + scatter in one edge pass ----
__global__ void k_fillb(const int* __restrict__ src, const int* __restrict__ dst) {
    int i = blockIdx.x * blockDim.x + threadIdx.x;
    if (i < N_EDGES) {
        int d = dst[i];
        int p = atomicAdd(&g_cnt[d], 1);
        if (p < CAP) g_adj[(size_t)d * CAP + p] = src[i];
    }
}

// ---- 3. layer-1 mean aggregation (warp/node, fp32) ----
__global__ void k_agg1(const float* __restrict__ x) {
    int w    = (blockIdx.x * blockDim.x + threadIdx.x) >> 5;
    int lane = threadIdx.x & 31;
    if (w >= N_NODES) return;
    int deg = g_cnt[w];
    if (deg > CAP) deg = CAP;
    const int* adj = g_adj + (size_t)w * CAP;
    float4 acc = make_float4(0.f, 0.f, 0.f, 0.f);
    for (int e = 0; e < deg; e++) {
        int s = adj[e];
        if (lane < IN_CH / 4) {
            float4 v = reinterpret_cast<const float4*>(x + (size_t)s * IN_CH)[lane];
            acc.x += v.x; acc.y += v.y; acc.z += v.z; acc.w += v.w;
        }
    }
    float inv = 1.f / fmaxf((float)deg, 1.f);
    if (lane < IN_CH / 4) {
        acc.x *= inv; acc.y *= inv; acc.z *= inv; acc.w *= inv;
        reinterpret_cast<float4*>(g_agg1 + (size_t)w * IN_CH)[lane] = acc;
    }
}

// ---- 4. layer-1 GEMM, tf32 mma, 4-stage cp.async pipeline, swizzled smem ----
__global__ void __launch_bounds__(256) k_gemm1(const float* __restrict__ x,
                                               const float* __restrict__ b1l) {
    __shared__ float sA[4][128 * 8];
    __shared__ float sB[4][8 * SB1];
    const int tid  = threadIdx.x;
    const int lane = tid & 31;
    const int warp = tid >> 5;
    const int wm   = warp & 3;
    const int wn   = warp >> 2;
    const int gr   = lane >> 2;
    const int kc   = lane & 3;
    const int row0 = blockIdx.x * 128;

    const int srow = tid >> 1;                 // 0..127
    const int skq  = (tid & 1) * 4;            // 0 or 4
    const int skqs = skq ^ swz(srow);          // swizzled half
    const int bk   = tid >> 5;                 // 0..7
    const int bn0  = (tid & 31) * 4;           // 0..124
    const int node = row0 + srow;

    auto issue = [&](int cc) {
        int st = cc & 3;
        int ks = cc * 8 + skq;
        const float* pa = g_agg1;
        bool va = false;
        if (node < N_NODES) {
            if (ks < IN_CH)                 { pa = g_agg1 + (size_t)node * IN_CH + ks; va = true; }
            else if (ks >= 104 && ks < 204) { pa = x + (size_t)node * IN_CH + (ks - 104); va = true; }
        }
        cpa16((uint32_t)__cvta_generic_to_shared(&sA[st][srow * 8 + skqs]), pa, va);
        cpa16((uint32_t)__cvta_generic_to_shared(&sB[st][bk * SB1 + bn0]),
              g_B1 + (cc * 8 + bk) * HID + bn0, true);
    };

    issue(0); cpa_commit();
    issue(1); cpa_commit();
    issue(2); cpa_commit();

    float acc[2][8][4];
#pragma unroll
    for (int mt = 0; mt < 2; mt++)
#pragma unroll
        for (int nt = 0; nt < 8; nt++)
#pragma unroll
            for (int j = 0; j < 4; j++) acc[mt][nt][j] = 0.f;

    const int sw0 = 4 * ((gr & 1) ^ ((gr >> 2) & 1));   // swizzle for row gr (and gr+8)
    const int p0  = kc ^ sw0;                            // col kc slot
    const int p1  = p0 ^ 4;                              // col kc+4 slot

#pragma unroll 1
    for (int c = 0; c < K1C; c++) {
        cpa_wait2();
        __syncthreads();
        const float* A = sA[c & 3];
        const float* B = sB[c & 3];

        uint32_t afr[2][4];
#pragma unroll
        for (int mt = 0; mt < 2; mt++) {
            int ar = wm * 32 + mt * 16 + gr;
            afr[mt][0] = __float_as_uint(A[ar * 8 + p0]);
            afr[mt][1] = __float_as_uint(A[(ar + 8) * 8 + p0]);
            afr[mt][2] = __float_as_uint(A[ar * 8 + p1]);
            afr[mt][3] = __float_as_uint(A[(ar + 8) * 8 + p1]);
        }
#pragma unroll
        for (int nt = 0; nt < 8; nt++) {
            int bc = wn * 64 + nt * 8 + gr;
            uint32_t b0 = __float_as_uint(B[kc * SB1 + bc]);
            uint32_t b1 = __float_as_uint(B[(kc + 4) * SB1 + bc]);
            mma_tf32(acc[0][nt], afr[0][0], afr[0][1], afr[0][2], afr[0][3], b0, b1);
            mma_tf32(acc[1][nt], afr[1][0], afr[1][1], afr[1][2], afr[1][3], b0, b1);
        }

        if (c + 3 < K1C) issue(c + 3);
        cpa_commit();
    }

#pragma unroll
    for (int mt = 0; mt < 2; mt++) {
#pragma unroll
        for (int nt = 0; nt < 8; nt++) {
            int col = wn * 64 + nt * 8 + 2 * kc;
            float2 bv = *reinterpret_cast<const float2*>(b1l + col);
            int r1 = row0 + wm * 32 + mt * 16 + gr;
            if (r1 < N_NODES) {
                float2 o = make_float2(acc[mt][nt][0] + bv.x, acc[mt][nt][1] + bv.y);
                *reinterpret_cast<float2*>(g_h + (size_t)r1 * HID + col) = o;
            }
            int r2 = r1 + 8;
            if (r2 < N_NODES) {
                float2 o = make_float2(acc[mt][nt][2] + bv.x, acc[mt][nt][3] + bv.y);
                *reinterpret_cast<float2*>(g_h + (size_t)r2 * HID + col) = o;
            }
        }
    }
}

// ---- 5. layer-2 GEMM, tf32 mma, 4-stage cp.async pipeline, swizzled smem ----
__global__ void __launch_bounds__(256) k_gemm2(const float* __restrict__ b2) {
    __shared__ float sA[4][128 * 8];
    __shared__ float sB[4][8 * SB2];
    const int tid  = threadIdx.x;
    const int lane = tid & 31;
    const int warp = tid >> 5;
    const int wm   = warp & 3;
    const int wn   = warp >> 2;
    const int gr   = lane >> 2;
    const int kc   = lane & 3;
    const int row0 = blockIdx.x * 128;

    const int srow = tid >> 1;
    const int skq  = (tid & 1) * 4;
    const int skqs = skq ^ swz(srow);
    const bool doB = (tid < 192);
    const int bk   = tid / 24;
    const int bn0  = (tid % 24) * 4;
    const int node = row0 + srow;

    const bool active = (wn == 0) || (row0 < ORIG);

    auto issue = [&](int cc) {
        int st = cc & 3;
        bool va = (node < N_NODES);
        const float* pa = va ? (g_h + (size_t)node * HID + cc * 8 + skq) : g_h;
        cpa16((uint32_t)__cvta_generic_to_shared(&sA[st][srow * 8 + skqs]), pa, va);
        if (doB)
            cpa16((uint32_t)__cvta_generic_to_shared(&sB[st][bk * SB2 + bn0]),
                  g_B2 + (cc * 8 + bk) * N2 + bn0, true);
    };

    issue(0); cpa_commit();
    issue(1); cpa_commit();
    issue(2); cpa_commit();

    float acc[2][6][4];
#pragma unroll
    for (int mt = 0; mt < 2; mt++)
#pragma unroll
        for (int nt = 0; nt < 6; nt++)
#pragma unroll
            for (int j = 0; j < 4; j++) acc[mt][nt][j] = 0.f;

    const int sw0 = 4 * ((gr & 1) ^ ((gr >> 2) & 1));
    const int p0  = kc ^ sw0;
    const int p1  = p0 ^ 4;

#pragma unroll 1
    for (int c = 0; c < K2C; c++) {
        cpa_wait2();
        __syncthreads();
        const float* A = sA[c & 3];
        const float* B = sB[c & 3];

        if (active) {
            uint32_t afr[2][4];
#pragma unroll
            for (int mt = 0; mt < 2; mt++) {
                int ar = wm * 32 + mt * 16 + gr;
                afr[mt][0] = __float_as_uint(A[ar * 8 + p0]);
                afr[mt][1] = __float_as_uint(A[(ar + 8) * 8 + p0]);
                afr[mt][2] = __float_as_uint(A[ar * 8 + p1]);
                afr[mt][3] = __float_as_uint(A[(ar + 8) * 8 + p1]);
            }
#pragma unroll
            for (int nt = 0; nt < 6; nt++) {
                int bc = wn * 48 + nt * 8 + gr;
                uint32_t b0 = __float_as_uint(B[kc * SB2 + bc]);
                uint32_t b1 = __float_as_uint(B[(kc + 4) * SB2 + bc]);
                mma_tf32(acc[0][nt], afr[0][0], afr[0][1], afr[0][2], afr[0][3], b0, b1);
                mma_tf32(acc[1][nt], afr[1][0], afr[1][1], afr[1][2], afr[1][3], b0, b1);
            }
        }

        if (c + 3 < K2C) issue(c + 3);
        cpa_commit();
    }

    if (!active) return;

#pragma unroll
    for (int mt = 0; mt < 2; mt++) {
#pragma unroll
        for (int nt = 0; nt < 6; nt++) {
            int colL = nt * 8 + 2 * kc;
            int r1 = row0 + wm * 32 + mt * 16 + gr;
            int r2 = r1 + 8;
            if (wn == 0) {
                if (r1 < N_NODES)
                    *reinterpret_cast<float2*>(g_g0 + (size_t)r1 * OUT_P + colL) =
                        make_float2(acc[mt][nt][0], acc[mt][nt][1]);
                if (r2 < N_NODES)
                    *reinterpret_cast<float2*>(g_g0 + (size_t)r2 * OUT_P + colL) =
                        make_float2(acc[mt][nt][2], acc[mt][nt][3]);
            } else {
                float bx = b2[colL];
                float by = (colL + 1 < OUT_CH) ? b2[colL + 1] : 0.f;
                if (r1 < ORIG)
                    *reinterpret_cast<float2*>(g_r0 + (size_t)r1 * OUT_P + colL) =
                        make_float2(acc[mt][nt][0] + bx, acc[mt][nt][1] + by);
                if (r2 < ORIG)
                    *reinterpret_cast<float2*>(g_r0 + (size_t)r2 * OUT_P + colL) =
                        make_float2(acc[mt][nt][2] + bx, acc[mt][nt][3] + by);
            }
        }
    }
}

// ---- 6. final: out = log_softmax(mean_nbr(g0) + r0)  for i < ORIG ----
__global__ void k_final(float* __restrict__ out) {
    int w    = (blockIdx.x * blockDim.x + threadIdx.x) >> 5;
    int lane = threadIdx.x & 31;
    if (w >= ORIG) return;
    int deg = g_cnt[w];
    if (deg > CAP) deg = CAP;
    const int* adj = g_adj + (size_t)w * CAP;
    float a0 = 0.f, a1 = 0.f;
    for (int e = 0; e < deg; e++) {
        int s = adj[e];
        const float* row = g_g0 + (size_t)s * OUT_P;
        a0 += __ldg(row + lane);
        if (lane < OUT_CH - 32) a1 += __ldg(row + 32 + lane);
    }
    float inv = 1.f / fmaxf((float)deg, 1.f);
    const float* r0row = g_r0 + (size_t)w * OUT_P;
    a0 = a0 * inv + r0row[lane];
    if (lane < OUT_CH - 32) a1 = a1 * inv + r0row[32 + lane];

    float m = a0;
    if (lane < OUT_CH - 32) m = fmaxf(m, a1);
#pragma unroll
    for (int o = 16; o > 0; o >>= 1) m = fmaxf(m, __shfl_xor_sync(0xffffffffu, m, o));
    float e0 = expf(a0 - m);
    float e1 = (lane < OUT_CH - 32) ? expf(a1 - m) : 0.f;
    float ss = e0 + e1;
#pragma unroll
    for (int o = 16; o > 0; o >>= 1) ss += __shfl_xor_sync(0xffffffffu, ss, o);
    float ls = m + logf(ss);
    out[(size_t)w * OUT_CH + lane] = a0 - ls;
    if (lane < OUT_CH - 32) out[(size_t)w * OUT_CH + 32 + lane] = a1 - ls;
}

extern "C" void kernel_launch(void* const* d_in, const int* in_sizes, int n_in,
                              void* d_out, int out_size) {
    const float* x   = (const float*)d_in[0];
    const int*   ei  = (const int*)  d_in[1];
    const int*   src = ei;
    const int*   dst = ei + N_EDGES;
    const float* w1l = (const float*)d_in[3];
    const float* b1l = (const float*)d_in[4];
    const float* w1r = (const float*)d_in[5];
    const float* w2l = (const float*)d_in[6];
    const float* b2l = (const float*)d_in[7];
    const float* w2r = (const float*)d_in[8];
    float* out = (float*)d_out;

    const int GB = (N_NODES + 127) / 128;   // 391

    k_pre   <<<PRE_NB, PRE_BS>>>(w1l, w1r, w2l, w2r);
    k_fillb <<<(N_EDGES + 255) / 256, 256>>>(src, dst);
    k_agg1  <<<(N_NODES * 32 + 255) / 256, 256>>>(x);
    k_gemm1 <<<GB, 256>>>(x, b1l);
    k_gemm2 <<<GB, 256>>>(b2l);
    k_final <<<(ORIG * 32 + 255) / 256, 256>>>(out);
}

// round 14
// speedup vs baseline: 1.2410x; 1.1038x over previous
#include <cuda_runtime.h>
#include <cstdint>

#define N_NODES 50000
#define N_EDGES 800000
#define IN_CH   100
#define HID     128
#define OUT_CH  47
#define OUT_P   48
#define ORIG    25000
#define CAP     96            // bucket capacity (max degree; Poisson(16) tail ~0)

#define PRE_NB  196
#define PRE_BS  256

#define K1   208          // padded K for layer1 (104 agg + 104 x)
#define K1C  (K1 / 8)     // 26 chunks
#define K2C  (HID / 8)    // 16 chunks
#define N2   96           // layer2 N: 48 g0-cols + 48 r0-cols
#define SB1  136          // sB row stride phase1 (mod 32 == 8 -> conflict-free)
#define SB2  104          // sB row stride phase2 (mod 32 == 8 -> conflict-free)

// dynamic smem layout (floats):
//   sA:  4 stages * 128*8          = 4096
//   sB:  4 stages * 8*SB1          = 4352   (phase2 reuses with stride SB2)
//   hT:  16 chunks * 128*8         = 16384
#define SMEM_FLOATS (4 * 128 * 8 + 4 * 8 * SB1 + 16 * 128 * 8)

// ---- scratch ----
__device__ int    g_cnt [N_NODES];
__device__ int    g_adj [(size_t)N_NODES * CAP];     // bucketed adjacency
__device__ float  g_agg1[(size_t)N_NODES * IN_CH];
__device__ float  g_g0  [(size_t)N_NODES * OUT_P];   // stride 48 (col 47 pad)
__device__ float  g_r0  [(size_t)ORIG * OUT_P];
__device__ float  g_B1  [K1 * HID];                  // tf32 [208][128]
__device__ float  g_B2  [HID * N2];                  // tf32 [128][96]

static __device__ __forceinline__ float to_tf32(float f) {
    uint32_t o;
    asm("cvt.rna.tf32.f32 %0, %1;" : "=r"(o) : "f"(f));
    return __uint_as_float(o);
}
static __device__ __forceinline__ void mma_tf32(float* c, uint32_t a0, uint32_t a1,
                                                uint32_t a2, uint32_t a3,
                                                uint32_t b0, uint32_t b1) {
    asm("mma.sync.aligned.m16n8k8.row.col.f32.tf32.tf32.f32 "
        "{%0,%1,%2,%3},{%4,%5,%6,%7},{%8,%9},{%0,%1,%2,%3};"
        : "+f"(c[0]), "+f"(c[1]), "+f"(c[2]), "+f"(c[3])
        : "r"(a0), "r"(a1), "r"(a2), "r"(a3), "r"(b0), "r"(b1));
}
static __device__ __forceinline__ void cpa16(uint32_t dst, const void* src, bool p) {
    int sz = p ? 16 : 0;
    asm volatile("cp.async.cg.shared.global [%0], [%1], 16, %2;"
                 :: "r"(dst), "l"(src), "r"(sz));
}
static __device__ __forceinline__ void cpa_commit() {
    asm volatile("cp.async.commit_group;");
}
static __device__ __forceinline__ void cpa_wait2() {
    asm volatile("cp.async.wait_group 2;");
}
// swizzle of the 16B half for row r: 0 or 4 floats
static __device__ __forceinline__ int swz(int r) {
    return 4 * ((r & 1) ^ ((r >> 2) & 1));
}

// ---- 1. zero counters + prepack B1/B2 (tf32) ----
__global__ void k_pre(const float* __restrict__ w1l, const float* __restrict__ w1r,
                      const float* __restrict__ w2l, const float* __restrict__ w2r) {
    int i = blockIdx.x * blockDim.x + threadIdx.x;
    if (i < N_NODES) g_cnt[i] = 0;
    if (i < K1 * HID) {
        int k = i / HID, c = i % HID;
        float v = 0.f;
        if (k < IN_CH)                         v = w1l[k * HID + c];
        else if (k >= 104 && k < 104 + IN_CH)  v = w1r[(k - 104) * HID + c];
        g_B1[i] = to_tf32(v);
    }
    if (i < HID * N2) {
        int k = i / N2, c = i % N2;
        float v = 0.f;
        if (c < OUT_CH)                        v = w2l[k * OUT_CH + c];
        else if (c >= 48 && c < 48 + OUT_CH)   v = w2r[k * OUT_CH + (c - 48)];
        g_B2[i] = to_tf32(v);
    }
}

// ---- 2. single-pass bucketed fill ----
__global__ void k_fillb(const int* __restrict__ src, const int* __restrict__ dst) {
    int i = blockIdx.x * blockDim.x + threadIdx.x;
    if (i < N_EDGES) {
        int d = dst[i];
        int p = atomicAdd(&g_cnt[d], 1);
        if (p < CAP) g_adj[(size_t)d * CAP + p] = src[i];
    }
}

// ---- 3. layer-1 mean aggregation (warp/node, fp32) ----
__global__ void k_agg1(const float* __restrict__ x) {
    int w    = (blockIdx.x * blockDim.x + threadIdx.x) >> 5;
    int lane = threadIdx.x & 31;
    if (w >= N_NODES) return;
    int deg = g_cnt[w];
    if (deg > CAP) deg = CAP;
    const int* adj = g_adj + (size_t)w * CAP;
    float4 acc = make_float4(0.f, 0.f, 0.f, 0.f);
    for (int e = 0; e < deg; e++) {
        int s = adj[e];
        if (lane < IN_CH / 4) {
            float4 v = reinterpret_cast<const float4*>(x + (size_t)s * IN_CH)[lane];
            acc.x += v.x; acc.y += v.y; acc.z += v.z; acc.w += v.w;
        }
    }
    float inv = 1.f / fmaxf((float)deg, 1.f);
    if (lane < IN_CH / 4) {
        acc.x *= inv; acc.y *= inv; acc.z *= inv; acc.w *= inv;
        reinterpret_cast<float4*>(g_agg1 + (size_t)w * IN_CH)[lane] = acc;
    }
}

// ---- 4. FUSED GEMM: phase1 h = [agg1|x]@B1+b1 (to smem), phase2 [g0|r0] = h@B2 ----
__global__ void __launch_bounds__(256, 2) k_gemmF(const float* __restrict__ x,
                                                  const float* __restrict__ b1l,
                                                  const float* __restrict__ b2) {
    extern __shared__ float smem[];
    float (*sA)[128 * 8]  = reinterpret_cast<float (*)[128 * 8]>(smem);
    float (*sB)[8 * SB1]  = reinterpret_cast<float (*)[8 * SB1]>(smem + 4 * 128 * 8);
    float* hT             = smem + 4 * 128 * 8 + 4 * 8 * SB1;   // [16][128*8]

    const int tid  = threadIdx.x;
    const int lane = tid & 31;
    const int warp = tid >> 5;
    const int wm   = warp & 3;
    const int wn   = warp >> 2;
    const int gr   = lane >> 2;
    const int kc   = lane & 3;
    const int row0 = blockIdx.x * 128;

    const int srow = tid >> 1;                 // 0..127
    const int skq  = (tid & 1) * 4;            // 0 or 4
    const int skqs = skq ^ swz(srow);          // swizzled half
    const int bk1  = tid >> 5;                 // 0..7
    const int bn1  = (tid & 31) * 4;           // 0..124
    const int node = row0 + srow;

    // phase-2 B staging mapping
    const bool doB2 = (tid < 192);
    const int bk2   = tid / 24;                // 0..7
    const int bn2   = (tid % 24) * 4;          // 0..92

    const int sw0 = 4 * ((gr & 1) ^ ((gr >> 2) & 1));
    const int p0  = kc ^ sw0;
    const int p1  = p0 ^ 4;

    // ===== phase 1 =====
    auto issue1 = [&](int cc) {
        int st = cc & 3;
        int ks = cc * 8 + skq;
        const float* pa = g_agg1;
        bool va = false;
        if (node < N_NODES) {
            if (ks < IN_CH)                 { pa = g_agg1 + (size_t)node * IN_CH + ks; va = true; }
            else if (ks >= 104 && ks < 204) { pa = x + (size_t)node * IN_CH + (ks - 104); va = true; }
        }
        cpa16((uint32_t)__cvta_generic_to_shared(&sA[st][srow * 8 + skqs]), pa, va);
        cpa16((uint32_t)__cvta_generic_to_shared(&sB[st][bk1 * SB1 + bn1]),
              g_B1 + (cc * 8 + bk1) * HID + bn1, true);
    };

    issue1(0); cpa_commit();
    issue1(1); cpa_commit();
    issue1(2); cpa_commit();

    float acc[2][8][4];
#pragma unroll
    for (int mt = 0; mt < 2; mt++)
#pragma unroll
        for (int nt = 0; nt < 8; nt++)
#pragma unroll
            for (int j = 0; j < 4; j++) acc[mt][nt][j] = 0.f;

#pragma unroll 1
    for (int c = 0; c < K1C; c++) {
        cpa_wait2();
        __syncthreads();
        const float* A = sA[c & 3];
        const float* B = sB[c & 3];

        uint32_t afr[2][4];
#pragma unroll
        for (int mt = 0; mt < 2; mt++) {
            int ar = wm * 32 + mt * 16 + gr;
            afr[mt][0] = __float_as_uint(A[ar * 8 + p0]);
            afr[mt][1] = __float_as_uint(A[(ar + 8) * 8 + p0]);
            afr[mt][2] = __float_as_uint(A[ar * 8 + p1]);
            afr[mt][3] = __float_as_uint(A[(ar + 8) * 8 + p1]);
        }
#pragma unroll
        for (int nt = 0; nt < 8; nt++) {
            int bc = wn * 64 + nt * 8 + gr;
            uint32_t b0 = __float_as_uint(B[kc * SB1 + bc]);
            uint32_t b1 = __float_as_uint(B[(kc + 4) * SB1 + bc]);
            mma_tf32(acc[0][nt], afr[0][0], afr[0][1], afr[0][2], afr[0][3], b0, b1);
            mma_tf32(acc[1][nt], afr[1][0], afr[1][1], afr[1][2], afr[1][3], b0, b1);
        }

        if (c + 3 < K1C) issue1(c + 3);
        cpa_commit();
    }

    // all warps done reading phase-1 stages before reuse
    __syncthreads();

    // ===== phase-2 B pipeline prologue (into reused sB stages, stride SB2) =====
    auto issue2 = [&](int cc) {
        int st = cc & 3;
        if (doB2)
            cpa16((uint32_t)__cvta_generic_to_shared(&sB[st][bk2 * SB2 + bn2]),
                  g_B2 + (cc * 8 + bk2) * N2 + bn2, true);
    };
    issue2(0); cpa_commit();
    issue2(1); cpa_commit();
    issue2(2); cpa_commit();

    // ===== phase-1 epilogue: h tile (+bias) -> hT in chunked swizzled layout =====
#pragma unroll
    for (int mt = 0; mt < 2; mt++) {
#pragma unroll
        for (int nt = 0; nt < 8; nt++) {
            int col = wn * 64 + nt * 8 + 2 * kc;
            int ch  = col >> 3;          // chunk = wn*8+nt
            int c8  = col & 7;           // 0,2,4,6
            float2 bv = *reinterpret_cast<const float2*>(b1l + col);
            int lr1 = wm * 32 + mt * 16 + gr;
            int lr2 = lr1 + 8;
            int s1 = ((c8 & 4) ^ swz(lr1)) + (c8 & 3);
            int s2 = ((c8 & 4) ^ swz(lr2)) + (c8 & 3);
            *reinterpret_cast<float2*>(&hT[ch * 1024 + lr1 * 8 + s1]) =
                make_float2(acc[mt][nt][0] + bv.x, acc[mt][nt][1] + bv.y);
            *reinterpret_cast<float2*>(&hT[ch * 1024 + lr2 * 8 + s2]) =
                make_float2(acc[mt][nt][2] + bv.x, acc[mt][nt][3] + bv.y);
        }
    }
    __syncthreads();   // hT visible to all

    // ===== phase 2 =====
    const bool active = (wn == 0) || (row0 < ORIG);

    float acc2[2][6][4];
#pragma unroll
    for (int mt = 0; mt < 2; mt++)
#pragma unroll
        for (int nt = 0; nt < 6; nt++)
#pragma unroll
            for (int j = 0; j < 4; j++) acc2[mt][nt][j] = 0.f;

#pragma unroll 1
    for (int c = 0; c < K2C; c++) {
        cpa_wait2();
        __syncthreads();
        const float* A = hT + c * 1024;
        const float* B = sB[c & 3];

        if (active) {
            uint32_t afr[2][4];
#pragma unroll
            for (int mt = 0; mt < 2; mt++) {
                int ar = wm * 32 + mt * 16 + gr;
                afr[mt][0] = __float_as_uint(A[ar * 8 + p0]);
                afr[mt][1] = __float_as_uint(A[(ar + 8) * 8 + p0]);
                afr[mt][2] = __float_as_uint(A[ar * 8 + p1]);
                afr[mt][3] = __float_as_uint(A[(ar + 8) * 8 + p1]);
            }
#pragma unroll
            for (int nt = 0; nt < 6; nt++) {
                int bc = wn * 48 + nt * 8 + gr;
                uint32_t b0 = __float_as_uint(B[kc * SB2 + bc]);
                uint32_t b1 = __float_as_uint(B[(kc + 4) * SB2 + bc]);
                mma_tf32(acc2[0][nt], afr[0][0], afr[0][1], afr[0][2], afr[0][3], b0, b1);
                mma_tf32(acc2[1][nt], afr[1][0], afr[1][1], afr[1][2], afr[1][3], b0, b1);
            }
        }

        if (c + 3 < K2C) issue2(c + 3);
        cpa_commit();
    }

    if (!active) return;

#pragma unroll
    for (int mt = 0; mt < 2; mt++) {
#pragma unroll
        for (int nt = 0; nt < 6; nt++) {
            int colL = nt * 8 + 2 * kc;
            int r1 = row0 + wm * 32 + mt * 16 + gr;
            int r2 = r1 + 8;
            if (wn == 0) {
                if (r1 < N_NODES)
                    *reinterpret_cast<float2*>(g_g0 + (size_t)r1 * OUT_P + colL) =
                        make_float2(acc2[mt][nt][0], acc2[mt][nt][1]);
                if (r2 < N_NODES)
                    *reinterpret_cast<float2*>(g_g0 + (size_t)r2 * OUT_P + colL) =
                        make_float2(acc2[mt][nt][2], acc2[mt][nt][3]);
            } else {
                float bx = b2[colL];
                float by = (colL + 1 < OUT_CH) ? b2[colL + 1] : 0.f;
                if (r1 < ORIG)
                    *reinterpret_cast<float2*>(g_r0 + (size_t)r1 * OUT_P + colL) =
                        make_float2(acc2[mt][nt][0] + bx, acc2[mt][nt][1] + by);
                if (r2 < ORIG)
                    *reinterpret_cast<float2*>(g_r0 + (size_t)r2 * OUT_P + colL) =
                        make_float2(acc2[mt][nt][2] + bx, acc2[mt][nt][3] + by);
            }
        }
    }
}

// ---- 5. final: out = log_softmax(mean_nbr(g0) + r0)  for i < ORIG ----
__global__ void k_final(float* __restrict__ out) {
    int w    = (blockIdx.x * blockDim.x + threadIdx.x) >> 5;
    int lane = threadIdx.x & 31;
    if (w >= ORIG) return;
    int deg = g_cnt[w];
    if (deg > CAP) deg = CAP;
    const int* adj = g_adj + (size_t)w * CAP;
    float a0 = 0.f, a1 = 0.f;
    for (int e = 0; e < deg; e++) {
        int s = adj[e];
        const float* row = g_g0 + (size_t)s * OUT_P;
        a0 += __ldg(row + lane);
        if (lane < OUT_CH - 32) a1 += __ldg(row + 32 + lane);
    }
    float inv = 1.f / fmaxf((float)deg, 1.f);
    const float* r0row = g_r0 + (size_t)w * OUT_P;
    a0 = a0 * inv + r0row[lane];
    if (lane < OUT_CH - 32) a1 = a1 * inv + r0row[32 + lane];

    float m = a0;
    if (lane < OUT_CH - 32) m = fmaxf(m, a1);
#pragma unroll
    for (int o = 16; o > 0; o >>= 1) m = fmaxf(m, __shfl_xor_sync(0xffffffffu, m, o));
    float e0 = expf(a0 - m);
    float e1 = (lane < OUT_CH - 32) ? expf(a1 - m) : 0.f;
    float ss = e0 + e1;
#pragma unroll
    for (int o = 16; o > 0; o >>= 1) ss += __shfl_xor_sync(0xffffffffu, ss, o);
    float ls = m + logf(ss);
    out[(size_t)w * OUT_CH + lane] = a0 - ls;
    if (lane < OUT_CH - 32) out[(size_t)w * OUT_CH + 32 + lane] = a1 - ls;
}

extern "C" void kernel_launch(void* const* d_in, const int* in_sizes, int n_in,
                              void* d_out, int out_size) {
    const float* x   = (const float*)d_in[0];
    const int*   ei  = (const int*)  d_in[1];
    const int*   src = ei;
    const int*   dst = ei + N_EDGES;
    const float* w1l = (const float*)d_in[3];
    const float* b1l = (const float*)d_in[4];
    const float* w1r = (const float*)d_in[5];
    const float* w2l = (const float*)d_in[6];
    const float* b2l = (const float*)d_in[7];
    const float* w2r = (const float*)d_in[8];
    float* out = (float*)d_out;

    const int GB = (N_NODES + 127) / 128;   // 391
    const int smem_bytes = SMEM_FLOATS * 4; // ~97 KB

    cudaFuncSetAttribute(k_gemmF, cudaFuncAttributeMaxDynamicSharedMemorySize, smem_bytes);

    k_pre   <<<PRE_NB, PRE_BS>>>(w1l, w1r, w2l, w2r);
    k_fillb <<<(N_EDGES + 255) / 256, 256>>>(src, dst);
    k_agg1  <<<(N_NODES * 32 + 255) / 256, 256>>>(x);
    k_gemmF <<<GB, 256, smem_bytes>>>(x, b1l, b2l);
    k_final <<<(ORIG * 32 + 255) / 256, 256>>>(out);
}